// round 6
// baseline (speedup 1.0000x reference)
#include <cuda_runtime.h>

// R6: single fused kernel. 32x32-element tiles, 4 elems/thread as 2 f32x2
// packed pairs, BC penalty fused into boundary tiles, last-block finalize.

#define NE 2048
#define NN 2049
#define BX 32
#define BYR 32
#define NBX (NE / BX)          // 64
#define NBY (NE / BYR)         // 64
#define NBLK (NBX * NBY)       // 4096
#define TW (BX + 1)            // 33
#define TH (BYR + 1)           // 33

typedef unsigned long long u64p;

__device__ float        g_partials[NBLK];
__device__ unsigned int g_count = 0;   // self-resetting arrival counter

__device__ __forceinline__ u64p pk(float lo, float hi) {
    u64p r; asm("mov.b64 %0, {%1, %2};" : "=l"(r) : "f"(lo), "f"(hi)); return r;
}
__device__ __forceinline__ void upk(float& lo, float& hi, u64p v) {
    asm("mov.b64 {%0, %1}, %2;" : "=f"(lo), "=f"(hi) : "l"(v));
}
__device__ __forceinline__ u64p mul2(u64p a, u64p b) {
    u64p r; asm("mul.rn.f32x2 %0, %1, %2;" : "=l"(r) : "l"(a), "l"(b)); return r;
}
__device__ __forceinline__ u64p add2(u64p a, u64p b) {
    u64p r; asm("add.rn.f32x2 %0, %1, %2;" : "=l"(r) : "l"(a), "l"(b)); return r;
}
__device__ __forceinline__ u64p fma2(u64p a, u64p b, u64p c) {
    u64p r; asm("fma.rn.f32x2 %0, %1, %2, %3;" : "=l"(r) : "l"(a), "l"(b), "l"(c)); return r;
}
__device__ __forceinline__ float frcp(float x) {
    float r; asm("rcp.approx.f32 %0, %1;" : "=f"(r) : "f"(x)); return r;
}
__device__ __forceinline__ u64p spl(float x) { return pk(x, x); }
// a - b, exactly rounded, using only fma.f32x2
__device__ __forceinline__ u64p sub2(u64p a, u64p b, u64p neg1) { return fma2(b, neg1, a); }

__global__ __launch_bounds__(256, 3) void fem_fused_kernel(
    const float* __restrict__ disp,
    const float* __restrict__ bc_u_vals,
    const float* __restrict__ bc_v_vals,
    float* __restrict__ out)
{
    __shared__ float2 tile[TH][TW];
    __shared__ float  wred[8];
    __shared__ double dred[8];
    __shared__ unsigned int sIsLast;

    const int tid = threadIdx.x;
    const int bx  = blockIdx.x % NBX;
    const int by  = blockIdx.x / NBX;
    const int c0  = bx * BX;
    const int r0  = by * BYR;

    const float2* __restrict__ disp2 = (const float2*)disp;

    for (int i = tid; i < TH * TW; i += 256) {
        const int rr = i / TW;
        const int cc = i - rr * TW;
        tile[rr][cc] = __ldg(&disp2[(r0 + rr) * NN + (c0 + cc)]);
    }
    __syncthreads();

    const int tx = tid & 31;
    const int wy = tid >> 5;
    const int e0 = wy * 4;

    // ---- BC penalty (boundary-owning tiles; values already staged) ----
    float acc = 0.0f;
    if (bx == 0) {
        if (tid < 32) {
            const float du = tile[tid][0].x - bc_u_vals[r0 + tid];
            acc += 1.0e10f * du * du;
        }
        if (by == NBY - 1 && tid == 32) {
            const float du = tile[32][0].x - bc_u_vals[2048];
            acc += 1.0e10f * du * du;
        }
    }
    if (by == 0) {
        if (tid >= 64 && tid < 96) {
            const int cc = tid - 64;
            const float dv = tile[0][cc].y - bc_v_vals[c0 + cc];
            acc += 1.0e10f * dv * dv;
        }
        if (bx == NBX - 1 && tid == 96) {
            const float dv = tile[0][32].y - bc_v_vals[2048];
            acc += 1.0e10f * dv * dv;
        }
    }

    // ---- packed constants ----
    const float G = 0.57735026918962576f;
    const u64p P    = spl(1.0f + G);
    const u64p Mm   = spl(1.0f - G);
    const u64p ONE  = spl(1.0f);
    const u64p NEG1 = spl(-1.0f);
    const u64p NU2  = spl(0.3f);
    const u64p NUN2 = spl(-0.3f);
    const u64p KK   = spl(210000.0f / (1.0f - 0.09f));
    const u64p ESH  = spl(210000.0f / 1.3f);
    const u64p HALF = spl(0.5f);

    // gauss coefficient tables: ep=1+eta, em=1-eta, xp=1+xi, xm=1-xi
    // eta = {-g,-g,g,g}, xi = {-g,g,g,-g}
    const u64p epT[4] = {Mm, Mm, P,  P};
    const u64p emT[4] = {P,  P,  Mm, Mm};
    const u64p xpT[4] = {Mm, P,  P,  Mm};
    const u64p xmT[4] = {P,  Mm, Mm, P};

    u64p acc2 = 0ull;  // packed en^2 accumulator (+0.0f pair)

    #pragma unroll
    for (int k0 = 0; k0 < 4; k0 += 2) {
        const int kr = e0 + k0;
        const float2 a0 = tile[kr][tx],     a1 = tile[kr + 1][tx],     a2 = tile[kr + 2][tx];
        const float2 b0 = tile[kr][tx + 1], b1 = tile[kr + 1][tx + 1], b2 = tile[kr + 2][tx + 1];

        // element k0 in lo lane, k0+1 in hi lane
        const u64p u0p = pk(a0.x, a1.x);
        const u64p v0p = pk(a0.y, a1.y);
        const u64p v1p = pk(b0.y, b1.y);
        const u64p u2p = pk(b1.x, b2.x);
        const u64p v2p = pk(b1.y, b2.y);
        const u64p u3p = pk(a1.x, a2.x);
        const u64p v3p = pk(a1.y, a2.y);

        const u64p du23 = sub2(u2p, u3p, NEG1);
        const u64p bp   = add2(sub2(v1p, v0p, NEG1), ONE);
        const u64p bq   = add2(sub2(v2p, v3p, NEG1), ONE);
        const u64p cs   = add2(sub2(u2p, u0p, NEG1), ONE);
        const u64p ct   = add2(sub2(u3p, u0p, NEG1), ONE);
        const u64p dm   = sub2(v3p, v0p, NEG1);
        const u64p dn   = sub2(v2p, v1p, NEG1);

        u64p S0 = 0ull, S1 = 0ull;  // B0 = -S0, B1 = +S1
        #pragma unroll
        for (int i = 0; i < 4; ++i) {
            const u64p A  = mul2(epT[i], du23);
            const u64p Bv = fma2(epT[i], bq, mul2(emT[i], bp));
            const u64p Cv = fma2(xmT[i], ct, mul2(xpT[i], cs));
            const u64p Dv = fma2(xpT[i], dn, mul2(xmT[i], dm));
            const u64p det = sub2(mul2(A, Dv), mul2(Bv, Cv), NEG1);  // AD - BC
            float dl, dh; upk(dl, dh, det);
            const u64p inv = pk(frcp(dl), frcp(dh));                  // 1/(AD-BC)
            const u64p t0 = fma2(xmT[i], Cv, mul2(epT[i], Dv));       // ep*D + xm*C
            S0 = fma2(inv, t0, S0);
            const u64p t1 = fma2(xmT[i], A, mul2(epT[i], Bv));        // ep*B + xm*A
            S1 = fma2(inv, t1, S1);
        }

        // E = S0*u3 = -exx ; eyy = S1*v3
        const u64p E   = mul2(S0, u3p);
        const u64p eyy = mul2(S1, v3p);
        const u64p gam = sub2(eyy, E, NEG1);                 // exx + eyy
        const u64p sxx = mul2(KK, sub2(mul2(NU2, eyy), E, NEG1));   // kk*(exx + nu*eyy)
        const u64p syy = mul2(KK, fma2(NUN2, E, eyy));               // kk*(eyy + nu*exx)
        const u64p sxy = mul2(ESH, gam);
        // s = exx*sxx + eyy*syy + 2*gam*sxy = eyy*syy - E*sxx + 2*gam*sxy
        u64p s = sub2(mul2(eyy, syy), mul2(E, sxx), NEG1);
        s = fma2(add2(gam, gam), sxy, s);
        const u64p en = mul2(s, HALF);
        acc2 = fma2(en, en, acc2);
    }

    {
        float lo, hi; upk(lo, hi, acc2);
        acc += lo + hi;
    }

    // ---- block reduction ----
    #pragma unroll
    for (int o = 16; o; o >>= 1)
        acc += __shfl_xor_sync(0xffffffffu, acc, o);
    if ((tid & 31) == 0) wred[wy] = acc;
    __syncthreads();

    if (tid == 0) {
        float sblk = 0.0f;
        #pragma unroll
        for (int w = 0; w < 8; ++w) sblk += wred[w];
        g_partials[blockIdx.x] = sblk;
    }
    __threadfence();
    if (tid == 0) {
        const unsigned int old = atomicAdd(&g_count, 1u);
        sIsLast = (old == NBLK - 1) ? 1u : 0u;
        if (sIsLast) g_count = 0;     // reset for next graph replay
    }
    __syncthreads();

    // ---- last block finalizes ----
    if (sIsLast) {
        __threadfence();
        double d = 0.0;
        #pragma unroll
        for (int j = 0; j < NBLK / 256; ++j)
            d += (double)g_partials[tid + j * 256];
        #pragma unroll
        for (int o = 16; o; o >>= 1)
            d += __shfl_xor_sync(0xffffffffu, d, o);
        if ((tid & 31) == 0) dred[tid >> 5] = d;
        __syncthreads();
        if (tid == 0) {
            double t = 0.0;
            #pragma unroll
            for (int w = 0; w < 8; ++w) t += dred[w];
            out[0] = (float)t;
        }
    }
}

extern "C" void kernel_launch(void* const* d_in, const int* in_sizes, int n_in,
                              void* d_out, int out_size)
{
    const float* disp      = (const float*)d_in[0];
    const float* bc_u_vals = (const float*)d_in[4];
    const float* bc_v_vals = (const float*)d_in[6];
    float* out = (float*)d_out;

    fem_fused_kernel<<<NBLK, 256>>>(disp, bc_u_vals, bc_v_vals, out);
}

// round 7
// speedup vs baseline: 1.1440x; 1.1440x over previous
#include <cuda_runtime.h>

// R7: single fused scalar kernel. 32x32-element tiles, 4 elems/thread,
// Gauss-point sharing (A,B depend only on eta-sign; C,D only on xi-sign),
// BC penalty fused into boundary tiles, last-block fp64 finalize.

#define NE 2048
#define NN 2049
#define BX 32
#define BYR 32
#define NBX (NE / BX)          // 64
#define NBY (NE / BYR)         // 64
#define NBLK (NBX * NBY)       // 4096
#define TW (BX + 1)            // 33
#define TH (BYR + 1)           // 33

__device__ float        g_partials[NBLK];
__device__ unsigned int g_count = 0;   // self-resetting arrival counter

__device__ __forceinline__ float frcp(float x) {
    float r; asm("rcp.approx.f32 %0, %1;" : "=f"(r) : "f"(x)); return r;
}

__global__ __launch_bounds__(256, 6) void fem_fused_kernel(
    const float* __restrict__ disp,
    const float* __restrict__ bc_u_vals,
    const float* __restrict__ bc_v_vals,
    float* __restrict__ out)
{
    __shared__ float2 tile[TH][TW];
    __shared__ float  wred[8];
    __shared__ double dred[8];
    __shared__ unsigned int sIsLast;

    const int tid = threadIdx.x;
    const int bx  = blockIdx.x % NBX;
    const int by  = blockIdx.x / NBX;
    const int c0  = bx * BX;
    const int r0  = by * BYR;

    const float2* __restrict__ disp2 = (const float2*)disp;

    for (int i = tid; i < TH * TW; i += 256) {
        const int rr = i / TW;
        const int cc = i - rr * TW;
        tile[rr][cc] = __ldg(&disp2[(r0 + rr) * NN + (c0 + cc)]);
    }
    __syncthreads();

    const int tx = tid & 31;
    const int wy = tid >> 5;
    const int e0 = wy * 4;

    // ---- BC penalty (boundary-owning tiles; values already staged) ----
    float acc = 0.0f;
    if (bx == 0) {
        if (tid < 32) {
            const float du = tile[tid][0].x - bc_u_vals[r0 + tid];
            acc += 1.0e10f * du * du;
        }
        if (by == NBY - 1 && tid == 32) {
            const float du = tile[32][0].x - bc_u_vals[2048];
            acc += 1.0e10f * du * du;
        }
    }
    if (by == 0) {
        if (tid >= 64 && tid < 96) {
            const int cc = tid - 64;
            const float dv = tile[0][cc].y - bc_v_vals[c0 + cc];
            acc += 1.0e10f * dv * dv;
        }
        if (bx == NBX - 1 && tid == 96) {
            const float dv = tile[0][32].y - bc_v_vals[2048];
            acc += 1.0e10f * dv * dv;
        }
    }

    const float G = 0.57735026918962576f;
    const float P = 1.0f + G;          // 1 + 1/sqrt(3)
    const float M = 1.0f - G;          // 1 - 1/sqrt(3)
    const float KK  = 210000.0f / (1.0f - 0.09f);
    const float ESH = 210000.0f / 1.3f;

    // node rows for this thread's 4 vertically stacked elements
    float2 a[5], b[5];
    #pragma unroll
    for (int k = 0; k < 5; ++k) {
        a[k] = tile[e0 + k][tx];
        b[k] = tile[e0 + k][tx + 1];
    }

    #pragma unroll
    for (int k = 0; k < 4; ++k) {
        const float u0 = a[k].x,     v0 = a[k].y;
        const float v1 = b[k].y;
        const float u2 = b[k + 1].x, v2 = b[k + 1].y;
        const float u3 = a[k + 1].x, v3 = a[k + 1].y;

        const float du23 = u2 - u3;
        const float bp = (v1 - v0) + 1.0f;
        const float bq = (v2 - v3) + 1.0f;
        const float cs = (u2 - u0) + 1.0f;
        const float ct = (u3 - u0) + 1.0f;
        const float dm = v3 - v0;
        const float dn = v2 - v1;

        // Gauss-shared quantities (eta-sign for A,B; xi-sign for C,D).
        const float Am = M * du23, Ap = P * du23;
        const float Bm = fmaf(M, bq, P * bp);   // eta=-g
        const float Bp = fmaf(P, bq, M * bp);   // eta=+g
        const float Cm = fmaf(P, ct, M * cs);   // xi=-g
        const float Cp = fmaf(M, ct, P * cs);   // xi=+g
        const float Dm = fmaf(M, dn, P * dm);   // xi=-g
        const float Dp = fmaf(P, dn, M * dm);   // xi=+g

        // points: 0:(eta-,xi-) 1:(eta-,xi+) 2:(eta+,xi+) 3:(eta+,xi-)
        const float r0i = frcp(fmaf(Am, Dm, -(Bm * Cm)));
        const float r1i = frcp(fmaf(Am, Dp, -(Bm * Cp)));
        const float r2i = frcp(fmaf(Ap, Dp, -(Bp * Cp)));
        const float r3i = frcp(fmaf(Ap, Dm, -(Bp * Cm)));

        // t0_i = ep_i*D_xi + xm_i*C_xi ; t1_i = ep_i*B_eta + xm_i*A_eta
        const float t00 = fmaf(M, Dm, P * Cm);
        const float t01 = M * (Dp + Cp);
        const float t02 = fmaf(P, Dp, M * Cp);
        const float t03 = P * (Dm + Cm);
        const float t10 = fmaf(M, Bm, P * Am);
        const float t11 = M * (Bm + Am);
        const float t12 = fmaf(P, Bp, M * Ap);
        const float t13 = P * (Bp + Ap);

        float S0 = t00 * r0i;            // B0 = -S0
        S0 = fmaf(t01, r1i, S0);
        S0 = fmaf(t02, r2i, S0);
        S0 = fmaf(t03, r3i, S0);
        float S1 = t10 * r0i;            // B1 = +S1
        S1 = fmaf(t11, r1i, S1);
        S1 = fmaf(t12, r2i, S1);
        S1 = fmaf(t13, r3i, S1);

        const float E   = S0 * u3;       // E = -exx
        const float eyy = S1 * v3;
        const float gam = eyy - E;       // exx + eyy
        const float sxx = KK  * fmaf(0.3f, eyy, -E);   // kk*(exx + nu*eyy)
        const float syy = KK  * fmaf(-0.3f, E, eyy);   // kk*(eyy + nu*exx)
        const float sxy = ESH * gam;
        float s = fmaf(eyy, syy, -(E * sxx));          // exx*sxx + eyy*syy
        s = fmaf(gam + gam, sxy, s);
        const float en = 0.5f * s;
        acc = fmaf(en, en, acc);
    }

    // ---- block reduction ----
    #pragma unroll
    for (int o = 16; o; o >>= 1)
        acc += __shfl_xor_sync(0xffffffffu, acc, o);
    if ((tid & 31) == 0) wred[wy] = acc;
    __syncthreads();

    if (tid == 0) {
        float sblk = 0.0f;
        #pragma unroll
        for (int w = 0; w < 8; ++w) sblk += wred[w];
        g_partials[blockIdx.x] = sblk;
    }
    __threadfence();
    if (tid == 0) {
        const unsigned int old = atomicAdd(&g_count, 1u);
        sIsLast = (old == NBLK - 1) ? 1u : 0u;
        if (sIsLast) g_count = 0;     // reset for next graph replay
    }
    __syncthreads();

    // ---- last block finalizes in fp64 ----
    if (sIsLast) {
        __threadfence();
        double d = 0.0;
        #pragma unroll
        for (int j = 0; j < NBLK / 256; ++j)
            d += (double)g_partials[tid + j * 256];
        #pragma unroll
        for (int o = 16; o; o >>= 1)
            d += __shfl_xor_sync(0xffffffffu, d, o);
        if ((tid & 31) == 0) dred[tid >> 5] = d;
        __syncthreads();
        if (tid == 0) {
            double t = 0.0;
            #pragma unroll
            for (int w = 0; w < 8; ++w) t += dred[w];
            out[0] = (float)t;
        }
    }
}

extern "C" void kernel_launch(void* const* d_in, const int* in_sizes, int n_in,
                              void* d_out, int out_size)
{
    const float* disp      = (const float*)d_in[0];
    const float* bc_u_vals = (const float*)d_in[4];
    const float* bc_v_vals = (const float*)d_in[6];
    float* out = (float*)d_out;

    fem_fused_kernel<<<NBLK, 256>>>(disp, bc_u_vals, bc_v_vals, out);
}

// round 8
// speedup vs baseline: 1.3346x; 1.1667x over previous
#include <cuda_runtime.h>

// R8: single fused kernel, NO shared-memory staging. Each warp: 4 element
// rows x 32 cols; column tx loaded direct (coalesced LDG.64), column tx+1
// via shfl (lane 31 loads halo). Gauss-point-shared algebra. BC fused.
// Release fence only on tid0; last block finalizes in fp64 via ld.cg.

#define NE 2048
#define NN 2049
#define NBX 64
#define NBY 64
#define NBLK (NBX * NBY)       // 4096

__device__ float        g_partials[NBLK];
__device__ unsigned int g_count = 0;   // self-resetting arrival counter

__device__ __forceinline__ float frcp(float x) {
    float r; asm("rcp.approx.f32 %0, %1;" : "=f"(r) : "f"(x)); return r;
}

__global__ __launch_bounds__(256, 6) void fem_fused_kernel(
    const float* __restrict__ disp,
    const float* __restrict__ bc_u_vals,
    const float* __restrict__ bc_v_vals,
    float* __restrict__ out)
{
    __shared__ float  wred[8];
    __shared__ double dred[8];
    __shared__ unsigned int sIsLast;

    const int tid = threadIdx.x;
    const int bx  = blockIdx.x % NBX;
    const int by  = blockIdx.x / NBX;
    const int c0  = bx * 32;
    const int tx  = tid & 31;
    const int wy  = tid >> 5;                 // warp id: 4 element rows each
    const int row0 = by * 32 + wy * 4;        // first node row for this warp

    const float2* __restrict__ disp2 = (const float2*)disp;
    const float2* __restrict__ base  = disp2 + (size_t)row0 * NN + c0;

    // 5 node rows, own column (coalesced, MLP=5)
    float2 a[5], b[5];
    #pragma unroll
    for (int k = 0; k < 5; ++k)
        a[k] = __ldg(base + (size_t)k * NN + tx);

    // neighbor column via shfl; lane 31 loads the halo column directly
    #pragma unroll
    for (int k = 0; k < 5; ++k) {
        b[k].x = __shfl_down_sync(0xffffffffu, a[k].x, 1);
        b[k].y = __shfl_down_sync(0xffffffffu, a[k].y, 1);
    }
    if (tx == 31) {
        #pragma unroll
        for (int k = 0; k < 5; ++k)
            b[k] = __ldg(base + (size_t)k * NN + 32);
    }

    // ---- BC penalty from registers ----
    float acc = 0.0f;
    if (bx == 0 && tx == 0) {                   // u BC: column 0, rows row0..row0+3
        #pragma unroll
        for (int k = 0; k < 4; ++k) {
            const float du = a[k].x - bc_u_vals[row0 + k];
            acc += 1.0e10f * du * du;
        }
        if (by == NBY - 1 && wy == 7) {         // node row 2048
            const float du = a[4].x - bc_u_vals[2048];
            acc += 1.0e10f * du * du;
        }
    }
    if (by == 0 && wy == 0) {                   // v BC: node row 0, cols c0+tx
        const float dv = a[0].y - bc_v_vals[c0 + tx];
        acc += 1.0e10f * dv * dv;
        if (bx == NBX - 1 && tx == 31) {        // node col 2048
            const float dv2 = b[0].y - bc_v_vals[2048];
            acc += 1.0e10f * dv2 * dv2;
        }
    }

    const float G = 0.57735026918962576f;
    const float P = 1.0f + G;
    const float M = 1.0f - G;
    const float KK  = 210000.0f / (1.0f - 0.09f);
    const float ESH = 210000.0f / 1.3f;

    #pragma unroll
    for (int k = 0; k < 4; ++k) {
        const float u0 = a[k].x,     v0 = a[k].y;
        const float v1 = b[k].y;
        const float u2 = b[k + 1].x, v2 = b[k + 1].y;
        const float u3 = a[k + 1].x, v3 = a[k + 1].y;

        const float du23 = u2 - u3;
        const float bp = (v1 - v0) + 1.0f;
        const float bq = (v2 - v3) + 1.0f;
        const float cs = (u2 - u0) + 1.0f;
        const float ct = (u3 - u0) + 1.0f;
        const float dm = v3 - v0;
        const float dn = v2 - v1;

        // Gauss-shared: A,B depend on eta-sign; C,D on xi-sign.
        const float Am = M * du23, Ap = P * du23;
        const float Bm = fmaf(M, bq, P * bp);
        const float Bp = fmaf(P, bq, M * bp);
        const float Cm = fmaf(P, ct, M * cs);
        const float Cp = fmaf(M, ct, P * cs);
        const float Dm = fmaf(M, dn, P * dm);
        const float Dp = fmaf(P, dn, M * dm);

        const float r0i = frcp(fmaf(Am, Dm, -(Bm * Cm)));
        const float r1i = frcp(fmaf(Am, Dp, -(Bm * Cp)));
        const float r2i = frcp(fmaf(Ap, Dp, -(Bp * Cp)));
        const float r3i = frcp(fmaf(Ap, Dm, -(Bp * Cm)));

        const float t00 = fmaf(M, Dm, P * Cm);
        const float t01 = M * (Dp + Cp);
        const float t02 = fmaf(P, Dp, M * Cp);
        const float t03 = P * (Dm + Cm);
        const float t10 = fmaf(M, Bm, P * Am);
        const float t11 = M * (Bm + Am);
        const float t12 = fmaf(P, Bp, M * Ap);
        const float t13 = P * (Bp + Ap);

        float S0 = t00 * r0i;
        S0 = fmaf(t01, r1i, S0);
        S0 = fmaf(t02, r2i, S0);
        S0 = fmaf(t03, r3i, S0);
        float S1 = t10 * r0i;
        S1 = fmaf(t11, r1i, S1);
        S1 = fmaf(t12, r2i, S1);
        S1 = fmaf(t13, r3i, S1);

        const float E   = S0 * u3;       // -exx
        const float eyy = S1 * v3;
        const float gam = eyy - E;
        const float sxx = KK  * fmaf(0.3f, eyy, -E);
        const float syy = KK  * fmaf(-0.3f, E, eyy);
        const float sxy = ESH * gam;
        float s = fmaf(eyy, syy, -(E * sxx));
        s = fmaf(gam + gam, sxy, s);
        const float en = 0.5f * s;
        acc = fmaf(en, en, acc);
    }

    // ---- block reduction ----
    #pragma unroll
    for (int o = 16; o; o >>= 1)
        acc += __shfl_xor_sync(0xffffffffu, acc, o);
    if (tx == 0) wred[wy] = acc;
    __syncthreads();

    if (tid == 0) {
        float sblk = 0.0f;
        #pragma unroll
        for (int w = 0; w < 8; ++w) sblk += wred[w];
        g_partials[blockIdx.x] = sblk;
        __threadfence();                               // release (tid0 only)
        const unsigned int old = atomicAdd(&g_count, 1u);
        sIsLast = (old == NBLK - 1) ? 1u : 0u;
        if (sIsLast) g_count = 0;                      // reset for next replay
    }
    __syncthreads();

    // ---- last block finalizes in fp64 (L2 reads) ----
    if (sIsLast) {
        double d = 0.0;
        #pragma unroll
        for (int j = 0; j < NBLK / 256; ++j)
            d += (double)__ldcg(&g_partials[tid + j * 256]);
        #pragma unroll
        for (int o = 16; o; o >>= 1)
            d += __shfl_xor_sync(0xffffffffu, d, o);
        if (tx == 0) dred[wy] = d;
        __syncthreads();
        if (tid == 0) {
            double t = 0.0;
            #pragma unroll
            for (int w = 0; w < 8; ++w) t += dred[w];
            out[0] = (float)t;
        }
    }
}

extern "C" void kernel_launch(void* const* d_in, const int* in_sizes, int n_in,
                              void* d_out, int out_size)
{
    const float* disp      = (const float*)d_in[0];
    const float* bc_u_vals = (const float*)d_in[4];
    const float* bc_v_vals = (const float*)d_in[6];
    float* out = (float*)d_out;

    fem_fused_kernel<<<NBLK, 256>>>(disp, bc_u_vals, bc_v_vals, out);
}

// round 10
// speedup vs baseline: 1.4748x; 1.1050x over previous
#include <cuda_runtime.h>

// R9 (resubmitted): fused kernel, no smem staging, no shuffles. Each warp:
// 4 element rows x 32 cols; both node columns loaded directly (neighbor col
// hits L1). Algebra: Gauss-sign sharing + folded "+1" constants +
// quadratic-form epilogue. BC fused from registers. tid0-only release fence;
// last block finalizes in fp64 via ld.cg.

#define NE 2048
#define NN 2049
#define NBX 64
#define NBY 64
#define NBLK (NBX * NBY)       // 4096

__device__ float        g_partials[NBLK];
__device__ unsigned int g_count = 0;   // self-resetting arrival counter

__device__ __forceinline__ float frcp(float x) {
    float r; asm("rcp.approx.f32 %0, %1;" : "=f"(r) : "f"(x)); return r;
}

__global__ __launch_bounds__(256, 6) void fem_fused_kernel(
    const float* __restrict__ disp,
    const float* __restrict__ bc_u_vals,
    const float* __restrict__ bc_v_vals,
    float* __restrict__ out)
{
    __shared__ float  wred[8];
    __shared__ double dred[8];
    __shared__ unsigned int sIsLast;

    const int tid = threadIdx.x;
    const int bx  = blockIdx.x % NBX;
    const int by  = blockIdx.x / NBX;
    const int c0  = bx * 32;
    const int tx  = tid & 31;
    const int wy  = tid >> 5;                 // warp id: 4 element rows each
    const int row0 = by * 32 + wy * 4;        // first node row for this warp

    const float2* __restrict__ disp2 = (const float2*)disp;
    const float2* __restrict__ base  = disp2 + (size_t)row0 * NN + c0 + tx;

    // 5 node rows x 2 node columns, all direct loads (neighbor col = L1 hit).
    float2 a[5], b[5];
    #pragma unroll
    for (int k = 0; k < 5; ++k) {
        a[k] = base[(size_t)k * NN];
        b[k] = base[(size_t)k * NN + 1];
    }

    // ---- BC penalty from registers ----
    float acc = 0.0f;
    if (bx == 0 && tx == 0) {                   // u BC: column 0
        #pragma unroll
        for (int k = 0; k < 4; ++k) {
            const float du = a[k].x - bc_u_vals[row0 + k];
            acc += 1.0e10f * du * du;
        }
        if (by == NBY - 1 && wy == 7) {         // node row 2048
            const float du = a[4].x - bc_u_vals[2048];
            acc += 1.0e10f * du * du;
        }
    }
    if (by == 0 && wy == 0) {                   // v BC: node row 0
        const float dv = a[0].y - bc_v_vals[c0 + tx];
        acc += 1.0e10f * dv * dv;
        if (bx == NBX - 1 && tx == 31) {        // node col 2048
            const float dv2 = b[0].y - bc_v_vals[2048];
            acc += 1.0e10f * dv2 * dv2;
        }
    }

    const float G = 0.57735026918962576f;
    const float P = 1.0f + G;
    const float M = 1.0f - G;
    const float TWO = 2.0f;
    const float KK  = 210000.0f / (1.0f - 0.09f);
    const float ESH = 210000.0f / 1.3f;
    const float C1 = 0.5f * KK;        // * (exx^2 + eyy^2)
    const float C2 = -0.3f * KK;       // * h, where h = E*eyy = -(exx*eyy)
    const float C3 = ESH;              // * gam^2

    #pragma unroll
    for (int k = 0; k < 4; ++k) {
        const float u0 = a[k].x,     v0 = a[k].y;
        const float v1 = b[k].y;
        const float u2 = b[k + 1].x, v2 = b[k + 1].y;
        const float u3 = a[k + 1].x, v3 = a[k + 1].y;

        const float du23 = u2 - u3;
        const float dvp  = v1 - v0;        // bp - 1
        const float dvq  = v2 - v3;        // bq - 1
        const float du20 = u2 - u0;        // cs - 1
        const float du30 = u3 - u0;        // ct - 1
        const float dm   = v3 - v0;
        const float dn   = v2 - v1;

        // A,B depend on eta-sign; C,D on xi-sign. M+P == 2 exactly.
        const float Am = M * du23, Ap = P * du23;
        const float Bm = fmaf(M, dvq, fmaf(P, dvp, TWO));   // M*bq + P*bp
        const float Bp = fmaf(P, dvq, fmaf(M, dvp, TWO));
        const float Cm = fmaf(P, du30, fmaf(M, du20, TWO)); // P*ct + M*cs
        const float Cp = fmaf(M, du30, fmaf(P, du20, TWO));
        const float Dm = fmaf(M, dn, P * dm);
        const float Dp = fmaf(P, dn, M * dm);

        const float r0i = frcp(fmaf(Am, Dm, -(Bm * Cm)));
        const float r1i = frcp(fmaf(Am, Dp, -(Bm * Cp)));
        const float r2i = frcp(fmaf(Ap, Dp, -(Bp * Cp)));
        const float r3i = frcp(fmaf(Ap, Dm, -(Bp * Cm)));

        const float t00 = fmaf(M, Dm, P * Cm);
        const float t01 = M * (Dp + Cp);
        const float t02 = fmaf(P, Dp, M * Cp);
        const float t03 = P * (Dm + Cm);
        const float t10 = fmaf(M, Bm, P * Am);
        const float t11 = M * (Bm + Am);
        const float t12 = fmaf(P, Bp, M * Ap);
        const float t13 = P * (Bp + Ap);

        float S0 = t00 * r0i;              // B0 = -S0
        S0 = fmaf(t01, r1i, S0);
        S0 = fmaf(t02, r2i, S0);
        S0 = fmaf(t03, r3i, S0);
        float S1 = t10 * r0i;              // B1 = +S1
        S1 = fmaf(t11, r1i, S1);
        S1 = fmaf(t12, r2i, S1);
        S1 = fmaf(t13, r3i, S1);

        const float E   = S0 * u3;                 // -exx
        const float eyy = S1 * v3;
        const float gam = eyy - E;                 // exx + eyy
        const float h   = E * eyy;                 // -(exx*eyy)
        const float q   = fmaf(E, E, eyy * eyy);   // exx^2 + eyy^2
        const float g2  = gam * gam;
        const float en  = fmaf(C1, q, fmaf(C3, g2, C2 * h));
        acc = fmaf(en, en, acc);
    }

    // ---- block reduction ----
    #pragma unroll
    for (int o = 16; o; o >>= 1)
        acc += __shfl_xor_sync(0xffffffffu, acc, o);
    if (tx == 0) wred[wy] = acc;
    __syncthreads();

    if (tid == 0) {
        float sblk = 0.0f;
        #pragma unroll
        for (int w = 0; w < 8; ++w) sblk += wred[w];
        g_partials[blockIdx.x] = sblk;
        __threadfence();                               // release (tid0 only)
        const unsigned int old = atomicAdd(&g_count, 1u);
        sIsLast = (old == NBLK - 1) ? 1u : 0u;
        if (sIsLast) g_count = 0;                      // reset for next replay
    }
    __syncthreads();

    // ---- last block finalizes in fp64 (L2 reads) ----
    if (sIsLast) {
        double d = 0.0;
        #pragma unroll
        for (int j = 0; j < NBLK / 256; ++j)
            d += (double)__ldcg(&g_partials[tid + j * 256]);
        #pragma unroll
        for (int o = 16; o; o >>= 1)
            d += __shfl_xor_sync(0xffffffffu, d, o);
        if (tx == 0) dred[wy] = d;
        __syncthreads();
        if (tid == 0) {
            double t = 0.0;
            #pragma unroll
            for (int w = 0; w < 8; ++w) t += dred[w];
            out[0] = (float)t;
        }
    }
}

extern "C" void kernel_launch(void* const* d_in, const int* in_sizes, int n_in,
                              void* d_out, int out_size)
{
    const float* disp      = (const float*)d_in[0];
    const float* bc_u_vals = (const float*)d_in[4];
    const float* bc_v_vals = (const float*)d_in[6];
    float* out = (float*)d_out;

    fem_fused_kernel<<<NBLK, 256>>>(disp, bc_u_vals, bc_v_vals, out);
}

// round 11
// speedup vs baseline: 1.5118x; 1.0251x over previous
#include <cuda_runtime.h>

// R11: persistent fused kernel. 888 blocks (148 SM x 6 CTA) x 256 threads;
// each block loops over 32x32-element tiles (4096 total). Per-thread fp32
// accumulator across tiles; one double partial per block; last of 888
// blocks finalizes in fp64. No smem staging, no shuffles in the mainloop.

#define NE 2048
#define NN 2049
#define NBX 64
#define NTILES 4096
#define NPBLK 888              // 148 * 6 persistent blocks

__device__ double       g_partials[NPBLK];
__device__ unsigned int g_count = 0;   // self-resetting arrival counter

__device__ __forceinline__ float frcp(float x) {
    float r; asm("rcp.approx.f32 %0, %1;" : "=f"(r) : "f"(x)); return r;
}

__global__ __launch_bounds__(256, 6) void fem_fused_kernel(
    const float* __restrict__ disp,
    const float* __restrict__ bc_u_vals,
    const float* __restrict__ bc_v_vals,
    float* __restrict__ out)
{
    __shared__ double dred[8];
    __shared__ unsigned int sIsLast;

    const int tid = threadIdx.x;
    const int tx  = tid & 31;
    const int wy  = tid >> 5;

    const float G = 0.57735026918962576f;
    const float P = 1.0f + G;
    const float M = 1.0f - G;
    const float TWO = 2.0f;
    const float KK  = 210000.0f / (1.0f - 0.09f);
    const float C1 = 0.5f * KK;        // * (exx^2 + eyy^2)
    const float C2 = -0.3f * KK;       // * h, h = E*eyy = -(exx*eyy)
    const float C3 = 210000.0f / 1.3f; // * gam^2

    const float2* __restrict__ disp2 = (const float2*)disp;

    float acc = 0.0f;

    for (int t = blockIdx.x; t < NTILES; t += NPBLK) {
        const int bx = t & (NBX - 1);
        const int by = t >> 6;
        const int c0 = bx * 32;
        const int row0 = by * 32 + wy * 4;

        const float2* __restrict__ base = disp2 + (size_t)row0 * NN + c0 + tx;

        // 5 node rows x 2 node columns (neighbor column = L1 hit).
        float2 a[5], b[5];
        #pragma unroll
        for (int k = 0; k < 5; ++k) {
            a[k] = base[(size_t)k * NN];
            b[k] = base[(size_t)k * NN + 1];
        }

        // ---- BC penalty from registers ----
        if (bx == 0 && tx == 0) {                   // u BC: column 0
            #pragma unroll
            for (int k = 0; k < 4; ++k) {
                const float du = a[k].x - bc_u_vals[row0 + k];
                acc += 1.0e10f * du * du;
            }
            if (by == 63 && wy == 7) {              // node row 2048
                const float du = a[4].x - bc_u_vals[2048];
                acc += 1.0e10f * du * du;
            }
        }
        if (by == 0 && wy == 0) {                   // v BC: node row 0
            const float dv = a[0].y - bc_v_vals[c0 + tx];
            acc += 1.0e10f * dv * dv;
            if (bx == NBX - 1 && tx == 31) {        // node col 2048
                const float dv2 = b[0].y - bc_v_vals[2048];
                acc += 1.0e10f * dv2 * dv2;
            }
        }

        // shared horizontal v-diffs: z[k] = b[k].y - a[k].y  (dvp(k), dvq(k)=z[k+1])
        float z[5];
        #pragma unroll
        for (int k = 0; k < 5; ++k) z[k] = b[k].y - a[k].y;

        #pragma unroll
        for (int k = 0; k < 4; ++k) {
            const float u0 = a[k].x;
            const float u2 = b[k + 1].x;
            const float u3 = a[k + 1].x;
            const float v3 = a[k + 1].y;

            const float du23 = u2 - u3;
            const float dvp  = z[k];
            const float dvq  = z[k + 1];
            const float du30 = u3 - u0;
            const float du20 = du23 + du30;          // u2 - u0
            const float dm   = v3 - a[k].y;          // v3 - v0
            const float dn   = b[k + 1].y - b[k].y;  // v2 - v1

            const float Am = M * du23, Ap = P * du23;
            const float Bm = fmaf(M, dvq, fmaf(P, dvp, TWO));
            const float Bp = fmaf(P, dvq, fmaf(M, dvp, TWO));
            const float Cm = fmaf(P, du30, fmaf(M, du20, TWO));
            const float Cp = fmaf(M, du30, fmaf(P, du20, TWO));
            const float Dm = fmaf(M, dn, P * dm);
            const float Dp = fmaf(P, dn, M * dm);

            const float r0i = frcp(fmaf(Am, Dm, -(Bm * Cm)));
            const float r1i = frcp(fmaf(Am, Dp, -(Bm * Cp)));
            const float r2i = frcp(fmaf(Ap, Dp, -(Bp * Cp)));
            const float r3i = frcp(fmaf(Ap, Dm, -(Bp * Cm)));

            const float t00 = fmaf(M, Dm, P * Cm);
            const float t01 = M * (Dp + Cp);
            const float t02 = fmaf(P, Dp, M * Cp);
            const float t03 = P * (Dm + Cm);
            const float t10 = fmaf(M, Bm, P * Am);
            const float t11 = M * (Bm + Am);
            const float t12 = fmaf(P, Bp, M * Ap);
            const float t13 = P * (Bp + Ap);

            float S0 = t00 * r0i;              // B0 = -S0
            S0 = fmaf(t01, r1i, S0);
            S0 = fmaf(t02, r2i, S0);
            S0 = fmaf(t03, r3i, S0);
            float S1 = t10 * r0i;              // B1 = +S1
            S1 = fmaf(t11, r1i, S1);
            S1 = fmaf(t12, r2i, S1);
            S1 = fmaf(t13, r3i, S1);

            const float E   = S0 * u3;                 // -exx
            const float eyy = S1 * v3;
            const float gam = eyy - E;
            const float h   = E * eyy;
            const float q   = fmaf(E, E, eyy * eyy);
            const float g2  = gam * gam;
            const float en  = fmaf(C1, q, fmaf(C3, g2, C2 * h));
            acc = fmaf(en, en, acc);
        }
    }

    // ---- block reduction (once per block) ----
    #pragma unroll
    for (int o = 16; o; o >>= 1)
        acc += __shfl_xor_sync(0xffffffffu, acc, o);
    if (tx == 0) dred[wy] = (double)acc;
    __syncthreads();

    if (tid == 0) {
        double sblk = 0.0;
        #pragma unroll
        for (int w = 0; w < 8; ++w) sblk += dred[w];
        g_partials[blockIdx.x] = sblk;
        __threadfence();                               // release (tid0 only)
        const unsigned int old = atomicAdd(&g_count, 1u);
        sIsLast = (old == NPBLK - 1) ? 1u : 0u;
        if (sIsLast) g_count = 0;                      // reset for next replay
    }
    __syncthreads();

    // ---- last block finalizes in fp64 (L2 reads) ----
    if (sIsLast) {
        double d = 0.0;
        for (int i = tid; i < NPBLK; i += 256)
            d += __ldcg(&g_partials[i]);
        #pragma unroll
        for (int o = 16; o; o >>= 1)
            d += __shfl_xor_sync(0xffffffffu, d, o);
        if (tx == 0) dred[wy] = d;
        __syncthreads();
        if (tid == 0) {
            double tt = 0.0;
            #pragma unroll
            for (int w = 0; w < 8; ++w) tt += dred[w];
            out[0] = (float)tt;
        }
    }
}

extern "C" void kernel_launch(void* const* d_in, const int* in_sizes, int n_in,
                              void* d_out, int out_size)
{
    const float* disp      = (const float*)d_in[0];
    const float* bc_u_vals = (const float*)d_in[4];
    const float* bc_v_vals = (const float*)d_in[6];
    float* out = (float*)d_out;

    fem_fused_kernel<<<NPBLK, 256>>>(disp, bc_u_vals, bc_v_vals, out);
}